// round 8
// baseline (speedup 1.0000x reference)
#include <cuda_runtime.h>
#include <cstdint>
#include <cstddef>

#define B_  256
#define L_  2048
#define H_  128
#define H2_ 256
#define V_  32000

// ---------------- scratch (static device globals; no allocs allowed) ----------------
__device__ float g_h[(size_t)B_ * L_ * H_];   // encoded h_all [B,L,H]
__device__ float g_r[B_ * H_];
__device__ float g_r2[B_ * H_];

// ============================ mma helpers (baseline PTX) ============================
__device__ __forceinline__ uint32_t f2tf32(float x) {
    uint32_t r;
    asm("cvt.rna.tf32.f32 %0, %1;" : "=r"(r) : "f"(x));
    return r;
}
__device__ __forceinline__ void mma_tf32(float* c, const uint32_t* a, const uint32_t* b) {
    asm volatile("mma.sync.aligned.m16n8k8.row.col.f32.tf32.tf32.f32 "
        "{%0,%1,%2,%3}, {%4,%5,%6,%7}, {%8,%9}, {%0,%1,%2,%3};"
        : "+f"(c[0]), "+f"(c[1]), "+f"(c[2]), "+f"(c[3])
        : "r"(a[0]), "r"(a[1]), "r"(a[2]), "r"(a[3]), "r"(b[0]), "r"(b[1]));
}
__device__ __forceinline__ void tsplit(float x, uint32_t& h, uint32_t& m) {
    h = f2tf32(x);
    m = f2tf32(x - __uint_as_float(h));
}

// ---------------- profiling-alignment dummy ----------------
__global__ void dummy_kernel() {}

// =====================================================================
// Encode (unchanged from R5/R6 — bit-identical output, passed)
// =====================================================================
#define EPAD 132
#define UPAD 260
#define WPAD1 132
#define WPAD2 68
#define OFF_E  0
#define OFF_U  (64 * EPAD)
#define OFF_WH (64 * EPAD + 64 * UPAD)
#define OFF_WM (OFF_WH + 8704)
#define ENC_FLOATS (OFF_WM + 8704)
#define ENC_SMEM (ENC_FLOATS * 4)

__global__ void __launch_bounds__(256, 1) encode_mma(
    const int*   __restrict__ seq,   const float* __restrict__ embed,
    const float* __restrict__ W1,    const float* __restrict__ b1,
    const float* __restrict__ W2,    const float* __restrict__ b2,
    const float* __restrict__ gamma, const float* __restrict__ beta)
{
    extern __shared__ float sm[];
    float*    eBuf = sm + OFF_E;
    float*    uBuf = sm + OFF_U;
    uint32_t* wh   = (uint32_t*)(sm + OFF_WH);
    uint32_t* wm   = (uint32_t*)(sm + OFF_WM);

    const int tid  = threadIdx.x;
    const int w    = tid >> 5, lane = tid & 31;
    const int wy   = w >> 1,   wx   = w & 1;
    const int gr   = lane >> 2, gc  = lane & 3;
    const int tok0 = blockIdx.x * 64;

    for (int i = tid; i < 64 * 128; i += 256) {
        int row = i >> 7, col = i & 127;
        int s = seq[tok0 + row];
        eBuf[row * EPAD + col] = embed[(size_t)s * 128 + col];
    }

    const int ar0 = (wy * 16 + gr) * EPAD;
    const int ar1 = (wy * 16 + gr + 8) * EPAD;

    for (int c = 0; c < 4; c++) {
        __syncthreads();
        for (int i = tid; i < 64 * 128; i += 256) {
            int n = i & 63, k = i >> 6;
            float v = W1[k * H2_ + 64 * c + n];
            uint32_t h, m;
            tsplit(v, h, m);
            wh[n * WPAD1 + k] = h;
            wm[n * WPAD1 + k] = m;
        }
        __syncthreads();

        float acc[4][4];
        #pragma unroll
        for (int nf = 0; nf < 4; nf++)
            #pragma unroll
            for (int j = 0; j < 4; j++) acc[nf][j] = 0.f;

        #pragma unroll 4
        for (int ks = 0; ks < 16; ks++) {
            int k0 = ks * 8;
            uint32_t ah[4], am[4];
            tsplit(eBuf[ar0 + k0 + gc],     ah[0], am[0]);
            tsplit(eBuf[ar1 + k0 + gc],     ah[1], am[1]);
            tsplit(eBuf[ar0 + k0 + 4 + gc], ah[2], am[2]);
            tsplit(eBuf[ar1 + k0 + 4 + gc], ah[3], am[3]);
            #pragma unroll
            for (int nf = 0; nf < 4; nf++) {
                int n = wx * 32 + nf * 8 + gr;
                uint32_t bh[2], bm[2];
                bh[0] = wh[n * WPAD1 + k0 + gc];
                bm[0] = wm[n * WPAD1 + k0 + gc];
                bh[1] = wh[n * WPAD1 + k0 + 4 + gc];
                bm[1] = wm[n * WPAD1 + k0 + 4 + gc];
                mma_tf32(acc[nf], ah, bh);
                mma_tf32(acc[nf], ah, bm);
                mma_tf32(acc[nf], am, bh);
                mma_tf32(acc[nf], am, bm);
            }
        }
        #pragma unroll
        for (int nf = 0; nf < 4; nf++)
            #pragma unroll
            for (int j = 0; j < 4; j++) {
                int row = wy * 16 + gr + ((j >> 1) ? 8 : 0);
                int col = 64 * c + wx * 32 + nf * 8 + gc * 2 + (j & 1);
                uBuf[row * UPAD + col] = fmaxf(acc[nf][j] + __ldg(b1 + col), 0.f);
            }
    }

    float acc2[8][4];
    #pragma unroll
    for (int nf = 0; nf < 8; nf++)
        #pragma unroll
        for (int j = 0; j < 4; j++) acc2[nf][j] = 0.f;

    const int ur0 = (wy * 16 + gr) * UPAD;
    const int ur1 = (wy * 16 + gr + 8) * UPAD;

    for (int c2 = 0; c2 < 4; c2++) {
        __syncthreads();
        for (int i = tid; i < 128 * 64; i += 256) {
            int n = i & 127, kk = i >> 7;
            float v = W2[(64 * c2 + kk) * H_ + n];
            uint32_t h, m;
            tsplit(v, h, m);
            wh[n * WPAD2 + kk] = h;
            wm[n * WPAD2 + kk] = m;
        }
        __syncthreads();

        #pragma unroll 4
        for (int ks = 0; ks < 8; ks++) {
            int kg = 64 * c2 + ks * 8;
            int kl = ks * 8;
            uint32_t ah[4], am[4];
            tsplit(uBuf[ur0 + kg + gc],     ah[0], am[0]);
            tsplit(uBuf[ur1 + kg + gc],     ah[1], am[1]);
            tsplit(uBuf[ur0 + kg + 4 + gc], ah[2], am[2]);
            tsplit(uBuf[ur1 + kg + 4 + gc], ah[3], am[3]);
            #pragma unroll
            for (int nf = 0; nf < 8; nf++) {
                int n = wx * 64 + nf * 8 + gr;
                uint32_t bh[2], bm[2];
                bh[0] = wh[n * WPAD2 + kl + gc];
                bm[0] = wm[n * WPAD2 + kl + gc];
                bh[1] = wh[n * WPAD2 + kl + 4 + gc];
                bm[1] = wm[n * WPAD2 + kl + 4 + gc];
                mma_tf32(acc2[nf], ah, bh);
                mma_tf32(acc2[nf], ah, bm);
                mma_tf32(acc2[nf], am, bh);
                mma_tf32(acc2[nf], am, bm);
            }
        }
    }

    __syncthreads();
    float* yBuf = (float*)wh;
    #pragma unroll
    for (int nf = 0; nf < 8; nf++)
        #pragma unroll
        for (int j = 0; j < 4; j++) {
            int row = wy * 16 + gr + ((j >> 1) ? 8 : 0);
            int col = wx * 64 + nf * 8 + gc * 2 + (j & 1);
            yBuf[row * EPAD + col] = acc2[nf][j] + __ldg(b2 + col) + eBuf[row * EPAD + col];
        }
    __syncthreads();

    #pragma unroll
    for (int rr = 0; rr < 8; rr++) {
        int row = w * 8 + rr;
        float v[4];
        #pragma unroll
        for (int q = 0; q < 4; q++) v[q] = yBuf[row * EPAD + lane + 32 * q];
        float s = v[0] + v[1] + v[2] + v[3];
        #pragma unroll
        for (int o = 16; o; o >>= 1) s += __shfl_xor_sync(0xffffffffu, s, o);
        float mu = s * (1.f / 128.f);
        float d[4], sq = 0.f;
        #pragma unroll
        for (int q = 0; q < 4; q++) { d[q] = v[q] - mu; sq = fmaf(d[q], d[q], sq); }
        #pragma unroll
        for (int o = 16; o; o >>= 1) sq += __shfl_xor_sync(0xffffffffu, sq, o);
        float inv = rsqrtf(sq * (1.f / 128.f) + 1e-5f);
        size_t base = (size_t)(tok0 + row) * H_;
        #pragma unroll
        for (int q = 0; q < 4; q++) {
            int col = lane + 32 * q;
            g_h[base + col] = d[q] * inv * __ldg(gamma + col) + __ldg(beta + col);
        }
    }
}

// =====================================================================
// Scan v4: warp-rebalanced, 2 barriers/step, bit-exact vs R1/R6.
// Warps 4-7 (tid>=128) do k staging + ||k||^2 reduce; warps 0-3 do phase 2.
// All 8 warps do matvec partials + gated update. Same expressions, same
// shuffle lane patterns -> bit-identical values.
// =====================================================================
__global__ void __launch_bounds__(256, 2) scan_kernel()
{
    __shared__ float k_s[2][128];
    __shared__ float red_k[2][4];
    __shared__ float err_s[128];
    __shared__ float red_e[4];
    __shared__ float vp_part[128][17];

    const int bb   = blockIdx.x;
    const int tid  = threadIdx.x;
    const int ty   = tid >> 4, tx = tid & 15;
    const int lane = tid & 31;
    const float* __restrict__ hb = g_h + (size_t)bb * L_ * H_;

    float M[8][8];
    #pragma unroll
    for (int r = 0; r < 8; r++)
        #pragma unroll
        for (int c = 0; c < 8; c++) M[r][c] = 0.f;

    float kn0 = 0.f, kn1 = 0.f;
    if (tid >= 128) {
        const int i = tid - 128;
        float kv = hb[i];                         // h[0]
        k_s[0][i] = kv;
        float p = kv * kv;
        #pragma unroll
        for (int o = 16; o; o >>= 1) p += __shfl_xor_sync(0xffffffffu, p, o);
        if (lane == 0) red_k[0][i >> 5] = p;
        kn0 = hb[128 + i];                        // h[1]
        kn1 = hb[256 + i];                        // h[2]
    }
    __syncthreads();

    for (int t = 0; t < L_ - 1; t++) {
        const int buf = t & 1;

        // ---- phase 1: matvec partials (all) ; staging+kk (warps 4-7) ----
        float kreg[8];
        #pragma unroll
        for (int c = 0; c < 8; c++) kreg[c] = k_s[buf][tx * 8 + c];
        #pragma unroll
        for (int r = 0; r < 8; r++) {
            float s = 0.f;
            #pragma unroll
            for (int c = 0; c < 8; c++) s = fmaf(M[r][c], kreg[c], s);
            vp_part[ty * 8 + r][tx] = s;
        }
        if (tid >= 128) {
            const int i = tid - 128;
            k_s[buf ^ 1][i] = kn0;                // h[t+1]
            float p = kn0 * kn0;                  // same value/order as R1's kv*kv
            #pragma unroll
            for (int o = 16; o; o >>= 1) p += __shfl_xor_sync(0xffffffffu, p, o);
            if (lane == 0) red_k[buf ^ 1][i >> 5] = p;
            kn0 = kn1;
            kn1 = (t + 3 < L_) ? hb[(size_t)(t + 3) * H_ + i] : 0.f;
        }
        __syncthreads();                          // A

        const float kk = red_k[buf][0] + red_k[buf][1] + red_k[buf][2] + red_k[buf][3];

        // ---- phase 2: row sums + err + e2 (warps 0-3) ----
        if (tid < 128) {
            float vp = 0.f;
            #pragma unroll
            for (int x = 0; x < 16; x++) vp += vp_part[tid][x];
            float e = k_s[buf][tid] - vp / (kk + 1e-6f);
            err_s[tid] = e;
            float p = e * e;
            #pragma unroll
            for (int o = 16; o; o >>= 1) p += __shfl_xor_sync(0xffffffffu, p, o);
            if (lane == 0) red_e[tid >> 5] = p;
        }
        __syncthreads();                          // B

        // ---- gated rank-1 update (all threads) ----
        float e2 = red_e[0] + red_e[1] + red_e[2] + red_e[3];
        if (sqrtf(e2) > 0.4f * sqrtf(kk)) {
            #pragma unroll
            for (int r = 0; r < 8; r++) {
                float er = err_s[ty * 8 + r];
                #pragma unroll
                for (int c = 0; c < 8; c++) M[r][c] = fmaf(er, kreg[c], M[r][c]);
            }
        }
    }

    // ---- final: r = M @ h[L-1] ----
    {
        const int buf = (L_ - 1) & 1;
        float kreg[8];
        #pragma unroll
        for (int c = 0; c < 8; c++) kreg[c] = k_s[buf][tx * 8 + c];
        #pragma unroll
        for (int r = 0; r < 8; r++) {
            float s = 0.f;
            #pragma unroll
            for (int c = 0; c < 8; c++) s = fmaf(M[r][c], kreg[c], s);
            vp_part[ty * 8 + r][tx] = s;
        }
        __syncthreads();
        if (tid < 128) {
            float vp = 0.f;
            #pragma unroll
            for (int x = 0; x < 16; x++) vp += vp_part[tid][x];
            g_r[bb * H_ + tid] = vp;
        }
    }
}

// =====================================================================
// Kernel 3: r2 = r @ Wrp + brp
// =====================================================================
__global__ void __launch_bounds__(256, 1) rproj_kernel(
    const float* __restrict__ Wrp, const float* __restrict__ brp)
{
    extern __shared__ float smf[];
    float* Rs = smf;
    float* Ws = smf + 64 * 132;
    const int tid = threadIdx.x, ty = tid >> 4, tx = tid & 15;
    const int m0 = blockIdx.x * 64;

    for (int i = tid; i < 64 * 128; i += 256) {
        int r = i >> 7, c = i & 127;
        Rs[r * 132 + c] = g_r[(m0 + r) * H_ + c];
    }
    for (int i = tid; i < 128 * 128; i += 256) Ws[i] = Wrp[i];
    __syncthreads();

    float acc[4][8];
    #pragma unroll
    for (int r = 0; r < 4; r++)
        #pragma unroll
        for (int j = 0; j < 8; j++) acc[r][j] = 0.f;
    #pragma unroll 8
    for (int k = 0; k < 128; k++) {
        float a[4], bbv[8];
        #pragma unroll
        for (int r = 0; r < 4; r++) a[r] = Rs[(ty * 4 + r) * 132 + k];
        #pragma unroll
        for (int j = 0; j < 8; j++) bbv[j] = Ws[k * 128 + tx + 16 * j];
        #pragma unroll
        for (int r = 0; r < 4; r++)
            #pragma unroll
            for (int j = 0; j < 8; j++) acc[r][j] = fmaf(a[r], bbv[j], acc[r][j]);
    }
    #pragma unroll
    for (int r = 0; r < 4; r++)
        #pragma unroll
        for (int j = 0; j < 8; j++) {
            int rr = m0 + ty * 4 + r, cc = tx + 16 * j;
            g_r2[rr * H_ + cc] = acc[r][j] + brp[cc];
        }
}

// =====================================================================
// Kernel 4: out = r2 @ Wout + bout
// =====================================================================
__global__ void __launch_bounds__(256, 1) out_kernel(
    const float* __restrict__ Wout, const float* __restrict__ bout,
    float* __restrict__ out)
{
    extern __shared__ float smf[];
    float* Rs = smf;
    float* Ws = smf + 64 * 132;
    const int tid = threadIdx.x, ty = tid >> 4, tx = tid & 15;
    const int n0 = blockIdx.x * 128;
    const int m0 = blockIdx.y * 64;

    for (int i = tid; i < 64 * 128; i += 256) {
        int r = i >> 7, c = i & 127;
        Rs[r * 132 + c] = g_r2[(m0 + r) * H_ + c];
    }
    for (int i = tid; i < 128 * 128; i += 256) {
        int k = i >> 7, c = i & 127;
        Ws[i] = Wout[(size_t)k * V_ + n0 + c];
    }
    __syncthreads();

    float acc[4][8];
    #pragma unroll
    for (int r = 0; r < 4; r++)
        #pragma unroll
        for (int j = 0; j < 8; j++) acc[r][j] = 0.f;
    #pragma unroll 8
    for (int k = 0; k < 128; k++) {
        float a[4], bbv[8];
        #pragma unroll
        for (int r = 0; r < 4; r++) a[r] = Rs[(ty * 4 + r) * 132 + k];
        #pragma unroll
        for (int j = 0; j < 8; j++) bbv[j] = Ws[k * 128 + tx + 16 * j];
        #pragma unroll
        for (int r = 0; r < 4; r++)
            #pragma unroll
            for (int j = 0; j < 8; j++) acc[r][j] = fmaf(a[r], bbv[j], acc[r][j]);
    }
    #pragma unroll
    for (int r = 0; r < 4; r++)
        #pragma unroll
        for (int j = 0; j < 8; j++) {
            int rr = m0 + ty * 4 + r, cc = n0 + tx + 16 * j;
            out[(size_t)rr * V_ + cc] = acc[r][j] + bout[cc];
        }
}

// =====================================================================
// launcher
// =====================================================================
extern "C" void kernel_launch(void* const* d_in, const int* in_sizes, int n_in,
                              void* d_out, int out_size)
{
    const int*   seq   = (const int*)  d_in[0];
    const float* embed = (const float*)d_in[1];
    const float* W1    = (const float*)d_in[2];
    const float* b1    = (const float*)d_in[3];
    const float* W2    = (const float*)d_in[4];
    const float* b2    = (const float*)d_in[5];
    const float* gamma = (const float*)d_in[6];
    const float* beta  = (const float*)d_in[7];
    const float* Wrp   = (const float*)d_in[8];
    const float* brp   = (const float*)d_in[9];
    const float* Wout  = (const float*)d_in[10];
    const float* bout  = (const float*)d_in[11];
    float* out = (float*)d_out;

    const int PROJ_SMEM = (64 * 132 + 128 * 128) * 4;

    cudaFuncSetAttribute(encode_mma,   cudaFuncAttributeMaxDynamicSharedMemorySize, ENC_SMEM);
    cudaFuncSetAttribute(rproj_kernel, cudaFuncAttributeMaxDynamicSharedMemorySize, PROJ_SMEM);
    cudaFuncSetAttribute(out_kernel,   cudaFuncAttributeMaxDynamicSharedMemorySize, PROJ_SMEM);

    // profiling alignment: shift ncu's skip-window onto the scan/encode
    dummy_kernel<<<1, 32>>>();
    dummy_kernel<<<1, 32>>>();

    encode_mma<<<(B_ * L_) / 64, 256, ENC_SMEM>>>(seq, embed, W1, b1, W2, b2, gamma, beta);
    scan_kernel<<<B_, 256>>>();
    rproj_kernel<<<B_ / 64, 256, PROJ_SMEM>>>(Wrp, brp);
    out_kernel<<<dim3(V_ / 128, B_ / 64), 256, PROJ_SMEM>>>(Wout, bout, out);
}

// round 9
// speedup vs baseline: 1.0114x; 1.0114x over previous
#include <cuda_runtime.h>
#include <cstdint>
#include <cstddef>

#define B_  256
#define L_  2048
#define H_  128
#define H2_ 256
#define V_  32000

// ---------------- scratch (static device globals; no allocs allowed) ----------------
__device__ float g_h[(size_t)B_ * L_ * H_];   // encoded h_all [B,L,H]
__device__ float g_r[B_ * H_];
__device__ float g_r2[B_ * H_];

// ============================ mma helpers (baseline PTX) ============================
__device__ __forceinline__ uint32_t f2tf32(float x) {
    uint32_t r;
    asm("cvt.rna.tf32.f32 %0, %1;" : "=r"(r) : "f"(x));
    return r;
}
__device__ __forceinline__ void mma_tf32(float* c, const uint32_t* a, const uint32_t* b) {
    asm volatile("mma.sync.aligned.m16n8k8.row.col.f32.tf32.tf32.f32 "
        "{%0,%1,%2,%3}, {%4,%5,%6,%7}, {%8,%9}, {%0,%1,%2,%3};"
        : "+f"(c[0]), "+f"(c[1]), "+f"(c[2]), "+f"(c[3])
        : "r"(a[0]), "r"(a[1]), "r"(a[2]), "r"(a[3]), "r"(b[0]), "r"(b[1]));
}
__device__ __forceinline__ void tsplit(float x, uint32_t& h, uint32_t& m) {
    h = f2tf32(x);
    m = f2tf32(x - __uint_as_float(h));
}

// ============ packed f32x2 helpers (FFMA2 — Blackwell, PTX-only path) ============
__device__ __forceinline__ uint64_t pk2(float lo, float hi) {
    uint64_t r;
    asm("mov.b64 %0, {%1, %2};" : "=l"(r) : "f"(lo), "f"(hi));
    return r;
}
__device__ __forceinline__ void upk2(uint64_t v, float& lo, float& hi) {
    asm("mov.b64 {%0, %1}, %2;" : "=f"(lo), "=f"(hi) : "l"(v));
}
__device__ __forceinline__ uint64_t fma2(uint64_t a, uint64_t b, uint64_t c) {
    uint64_t d;
    asm("fma.rn.f32x2 %0, %1, %2, %3;" : "=l"(d) : "l"(a), "l"(b), "l"(c));
    return d;
}

// ---------------- profiling-alignment dummy ----------------
__global__ void dummy_kernel() {}

// =====================================================================
// Encode (unchanged — bit-identical output, passed R5-R7)
// =====================================================================
#define EPAD 132
#define UPAD 260
#define WPAD1 132
#define WPAD2 68
#define OFF_E  0
#define OFF_U  (64 * EPAD)
#define OFF_WH (64 * EPAD + 64 * UPAD)
#define OFF_WM (OFF_WH + 8704)
#define ENC_FLOATS (OFF_WM + 8704)
#define ENC_SMEM (ENC_FLOATS * 4)

__global__ void __launch_bounds__(256, 1) encode_mma(
    const int*   __restrict__ seq,   const float* __restrict__ embed,
    const float* __restrict__ W1,    const float* __restrict__ b1,
    const float* __restrict__ W2,    const float* __restrict__ b2,
    const float* __restrict__ gamma, const float* __restrict__ beta)
{
    extern __shared__ float sm[];
    float*    eBuf = sm + OFF_E;
    float*    uBuf = sm + OFF_U;
    uint32_t* wh   = (uint32_t*)(sm + OFF_WH);
    uint32_t* wm   = (uint32_t*)(sm + OFF_WM);

    const int tid  = threadIdx.x;
    const int w    = tid >> 5, lane = tid & 31;
    const int wy   = w >> 1,   wx   = w & 1;
    const int gr   = lane >> 2, gc  = lane & 3;
    const int tok0 = blockIdx.x * 64;

    for (int i = tid; i < 64 * 128; i += 256) {
        int row = i >> 7, col = i & 127;
        int s = seq[tok0 + row];
        eBuf[row * EPAD + col] = embed[(size_t)s * 128 + col];
    }

    const int ar0 = (wy * 16 + gr) * EPAD;
    const int ar1 = (wy * 16 + gr + 8) * EPAD;

    for (int c = 0; c < 4; c++) {
        __syncthreads();
        for (int i = tid; i < 64 * 128; i += 256) {
            int n = i & 63, k = i >> 6;
            float v = W1[k * H2_ + 64 * c + n];
            uint32_t h, m;
            tsplit(v, h, m);
            wh[n * WPAD1 + k] = h;
            wm[n * WPAD1 + k] = m;
        }
        __syncthreads();

        float acc[4][4];
        #pragma unroll
        for (int nf = 0; nf < 4; nf++)
            #pragma unroll
            for (int j = 0; j < 4; j++) acc[nf][j] = 0.f;

        #pragma unroll 4
        for (int ks = 0; ks < 16; ks++) {
            int k0 = ks * 8;
            uint32_t ah[4], am[4];
            tsplit(eBuf[ar0 + k0 + gc],     ah[0], am[0]);
            tsplit(eBuf[ar1 + k0 + gc],     ah[1], am[1]);
            tsplit(eBuf[ar0 + k0 + 4 + gc], ah[2], am[2]);
            tsplit(eBuf[ar1 + k0 + 4 + gc], ah[3], am[3]);
            #pragma unroll
            for (int nf = 0; nf < 4; nf++) {
                int n = wx * 32 + nf * 8 + gr;
                uint32_t bh[2], bm[2];
                bh[0] = wh[n * WPAD1 + k0 + gc];
                bm[0] = wm[n * WPAD1 + k0 + gc];
                bh[1] = wh[n * WPAD1 + k0 + 4 + gc];
                bm[1] = wm[n * WPAD1 + k0 + 4 + gc];
                mma_tf32(acc[nf], ah, bh);
                mma_tf32(acc[nf], ah, bm);
                mma_tf32(acc[nf], am, bh);
                mma_tf32(acc[nf], am, bm);
            }
        }
        #pragma unroll
        for (int nf = 0; nf < 4; nf++)
            #pragma unroll
            for (int j = 0; j < 4; j++) {
                int row = wy * 16 + gr + ((j >> 1) ? 8 : 0);
                int col = 64 * c + wx * 32 + nf * 8 + gc * 2 + (j & 1);
                uBuf[row * UPAD + col] = fmaxf(acc[nf][j] + __ldg(b1 + col), 0.f);
            }
    }

    float acc2[8][4];
    #pragma unroll
    for (int nf = 0; nf < 8; nf++)
        #pragma unroll
        for (int j = 0; j < 4; j++) acc2[nf][j] = 0.f;

    const int ur0 = (wy * 16 + gr) * UPAD;
    const int ur1 = (wy * 16 + gr + 8) * UPAD;

    for (int c2 = 0; c2 < 4; c2++) {
        __syncthreads();
        for (int i = tid; i < 128 * 64; i += 256) {
            int n = i & 127, kk = i >> 7;
            float v = W2[(64 * c2 + kk) * H_ + n];
            uint32_t h, m;
            tsplit(v, h, m);
            wh[n * WPAD2 + kk] = h;
            wm[n * WPAD2 + kk] = m;
        }
        __syncthreads();

        #pragma unroll 4
        for (int ks = 0; ks < 8; ks++) {
            int kg = 64 * c2 + ks * 8;
            int kl = ks * 8;
            uint32_t ah[4], am[4];
            tsplit(uBuf[ur0 + kg + gc],     ah[0], am[0]);
            tsplit(uBuf[ur1 + kg + gc],     ah[1], am[1]);
            tsplit(uBuf[ur0 + kg + 4 + gc], ah[2], am[2]);
            tsplit(uBuf[ur1 + kg + 4 + gc], ah[3], am[3]);
            #pragma unroll
            for (int nf = 0; nf < 8; nf++) {
                int n = wx * 64 + nf * 8 + gr;
                uint32_t bh[2], bm[2];
                bh[0] = wh[n * WPAD2 + kl + gc];
                bm[0] = wm[n * WPAD2 + kl + gc];
                bh[1] = wh[n * WPAD2 + kl + 4 + gc];
                bm[1] = wm[n * WPAD2 + kl + 4 + gc];
                mma_tf32(acc2[nf], ah, bh);
                mma_tf32(acc2[nf], ah, bm);
                mma_tf32(acc2[nf], am, bh);
                mma_tf32(acc2[nf], am, bm);
            }
        }
    }

    __syncthreads();
    float* yBuf = (float*)wh;
    #pragma unroll
    for (int nf = 0; nf < 8; nf++)
        #pragma unroll
        for (int j = 0; j < 4; j++) {
            int row = wy * 16 + gr + ((j >> 1) ? 8 : 0);
            int col = wx * 64 + nf * 8 + gc * 2 + (j & 1);
            yBuf[row * EPAD + col] = acc2[nf][j] + __ldg(b2 + col) + eBuf[row * EPAD + col];
        }
    __syncthreads();

    #pragma unroll
    for (int rr = 0; rr < 8; rr++) {
        int row = w * 8 + rr;
        float v[4];
        #pragma unroll
        for (int q = 0; q < 4; q++) v[q] = yBuf[row * EPAD + lane + 32 * q];
        float s = v[0] + v[1] + v[2] + v[3];
        #pragma unroll
        for (int o = 16; o; o >>= 1) s += __shfl_xor_sync(0xffffffffu, s, o);
        float mu = s * (1.f / 128.f);
        float d[4], sq = 0.f;
        #pragma unroll
        for (int q = 0; q < 4; q++) { d[q] = v[q] - mu; sq = fmaf(d[q], d[q], sq); }
        #pragma unroll
        for (int o = 16; o; o >>= 1) sq += __shfl_xor_sync(0xffffffffu, sq, o);
        float inv = rsqrtf(sq * (1.f / 128.f) + 1e-5f);
        size_t base = (size_t)(tok0 + row) * H_;
        #pragma unroll
        for (int q = 0; q < 4; q++) {
            int col = lane + 32 * q;
            g_h[base + col] = d[q] * inv * __ldg(gamma + col) + __ldg(beta + col);
        }
    }
}

// =====================================================================
// Scan v5: FFMA2-packed M (row pairs). Each f32x2 lane runs the SAME
// serial chain as the scalar version -> bit-identical values.
// Structure (barriers, reductions, gate) identical to v4 (passed).
// =====================================================================
__global__ void __launch_bounds__(256, 2) scan_kernel()
{
    __shared__ float k_s[2][128];
    __shared__ float red_k[2][4];
    __shared__ float err_s[128];
    __shared__ float red_e[4];
    __shared__ float vp_part[128][17];

    const int bb   = blockIdx.x;
    const int tid  = threadIdx.x;
    const int ty   = tid >> 4, tx = tid & 15;
    const int lane = tid & 31;
    const float* __restrict__ hb = g_h + (size_t)bb * L_ * H_;

    // M packed: M2[p][c] holds rows (ty*8+2p, ty*8+2p+1), column c
    uint64_t M2[4][8];
    #pragma unroll
    for (int p = 0; p < 4; p++)
        #pragma unroll
        for (int c = 0; c < 8; c++) M2[p][c] = 0ull;

    float kn0 = 0.f, kn1 = 0.f;
    if (tid >= 128) {
        const int i = tid - 128;
        float kv = hb[i];                         // h[0]
        k_s[0][i] = kv;
        float p = kv * kv;
        #pragma unroll
        for (int o = 16; o; o >>= 1) p += __shfl_xor_sync(0xffffffffu, p, o);
        if (lane == 0) red_k[0][i >> 5] = p;
        kn0 = hb[128 + i];                        // h[1]
        kn1 = hb[256 + i];                        // h[2]
    }
    __syncthreads();

    for (int t = 0; t < L_ - 1; t++) {
        const int buf = t & 1;

        // ---- phase 1: packed matvec partials (all) ; staging+kk (warps 4-7) ----
        float kreg[8];
        uint64_t k2[8];
        #pragma unroll
        for (int c = 0; c < 8; c++) {
            kreg[c] = k_s[buf][tx * 8 + c];
            k2[c]   = pk2(kreg[c], kreg[c]);      // broadcast pair
        }
        #pragma unroll
        for (int p = 0; p < 4; p++) {
            uint64_t s2 = 0ull;                   // (0.f, 0.f)
            #pragma unroll
            for (int c = 0; c < 8; c++) s2 = fma2(M2[p][c], k2[c], s2);
            float slo, shi;
            upk2(s2, slo, shi);
            vp_part[ty * 8 + 2 * p][tx]     = slo;
            vp_part[ty * 8 + 2 * p + 1][tx] = shi;
        }
        if (tid >= 128) {
            const int i = tid - 128;
            k_s[buf ^ 1][i] = kn0;                // h[t+1]
            float p = kn0 * kn0;
            #pragma unroll
            for (int o = 16; o; o >>= 1) p += __shfl_xor_sync(0xffffffffu, p, o);
            if (lane == 0) red_k[buf ^ 1][i >> 5] = p;
            kn0 = kn1;
            kn1 = (t + 3 < L_) ? hb[(size_t)(t + 3) * H_ + i] : 0.f;
        }
        __syncthreads();                          // A

        const float kk = red_k[buf][0] + red_k[buf][1] + red_k[buf][2] + red_k[buf][3];

        // ---- phase 2: row sums + err + e2 (warps 0-3) ----
        if (tid < 128) {
            float vp = 0.f;
            #pragma unroll
            for (int x = 0; x < 16; x++) vp += vp_part[tid][x];
            float e = k_s[buf][tid] - vp / (kk + 1e-6f);
            err_s[tid] = e;
            float p = e * e;
            #pragma unroll
            for (int o = 16; o; o >>= 1) p += __shfl_xor_sync(0xffffffffu, p, o);
            if (lane == 0) red_e[tid >> 5] = p;
        }
        __syncthreads();                          // B

        // ---- gated rank-1 update (all threads, packed) ----
        float e2 = red_e[0] + red_e[1] + red_e[2] + red_e[3];
        if (sqrtf(e2) > 0.4f * sqrtf(kk)) {
            #pragma unroll
            for (int p = 0; p < 4; p++) {
                uint64_t er2 = pk2(err_s[ty * 8 + 2 * p], err_s[ty * 8 + 2 * p + 1]);
                #pragma unroll
                for (int c = 0; c < 8; c++) M2[p][c] = fma2(er2, k2[c], M2[p][c]);
            }
        }
    }

    // ---- final: r = M @ h[L-1] (packed, same chains) ----
    {
        const int buf = (L_ - 1) & 1;
        uint64_t k2[8];
        #pragma unroll
        for (int c = 0; c < 8; c++) {
            float kv = k_s[buf][tx * 8 + c];
            k2[c] = pk2(kv, kv);
        }
        #pragma unroll
        for (int p = 0; p < 4; p++) {
            uint64_t s2 = 0ull;
            #pragma unroll
            for (int c = 0; c < 8; c++) s2 = fma2(M2[p][c], k2[c], s2);
            float slo, shi;
            upk2(s2, slo, shi);
            vp_part[ty * 8 + 2 * p][tx]     = slo;
            vp_part[ty * 8 + 2 * p + 1][tx] = shi;
        }
        __syncthreads();
        if (tid < 128) {
            float vp = 0.f;
            #pragma unroll
            for (int x = 0; x < 16; x++) vp += vp_part[tid][x];
            g_r[bb * H_ + tid] = vp;
        }
    }
}

// =====================================================================
// Kernel 3: r2 = r @ Wrp + brp
// =====================================================================
__global__ void __launch_bounds__(256, 1) rproj_kernel(
    const float* __restrict__ Wrp, const float* __restrict__ brp)
{
    extern __shared__ float smf[];
    float* Rs = smf;
    float* Ws = smf + 64 * 132;
    const int tid = threadIdx.x, ty = tid >> 4, tx = tid & 15;
    const int m0 = blockIdx.x * 64;

    for (int i = tid; i < 64 * 128; i += 256) {
        int r = i >> 7, c = i & 127;
        Rs[r * 132 + c] = g_r[(m0 + r) * H_ + c];
    }
    for (int i = tid; i < 128 * 128; i += 256) Ws[i] = Wrp[i];
    __syncthreads();

    float acc[4][8];
    #pragma unroll
    for (int r = 0; r < 4; r++)
        #pragma unroll
        for (int j = 0; j < 8; j++) acc[r][j] = 0.f;
    #pragma unroll 8
    for (int k = 0; k < 128; k++) {
        float a[4], bbv[8];
        #pragma unroll
        for (int r = 0; r < 4; r++) a[r] = Rs[(ty * 4 + r) * 132 + k];
        #pragma unroll
        for (int j = 0; j < 8; j++) bbv[j] = Ws[k * 128 + tx + 16 * j];
        #pragma unroll
        for (int r = 0; r < 4; r++)
            #pragma unroll
            for (int j = 0; j < 8; j++) acc[r][j] = fmaf(a[r], bbv[j], acc[r][j]);
    }
    #pragma unroll
    for (int r = 0; r < 4; r++)
        #pragma unroll
        for (int j = 0; j < 8; j++) {
            int rr = m0 + ty * 4 + r, cc = tx + 16 * j;
            g_r2[rr * H_ + cc] = acc[r][j] + brp[cc];
        }
}

// =====================================================================
// Kernel 4: out = r2 @ Wout + bout
// =====================================================================
__global__ void __launch_bounds__(256, 1) out_kernel(
    const float* __restrict__ Wout, const float* __restrict__ bout,
    float* __restrict__ out)
{
    extern __shared__ float smf[];
    float* Rs = smf;
    float* Ws = smf + 64 * 132;
    const int tid = threadIdx.x, ty = tid >> 4, tx = tid & 15;
    const int n0 = blockIdx.x * 128;
    const int m0 = blockIdx.y * 64;

    for (int i = tid; i < 64 * 128; i += 256) {
        int r = i >> 7, c = i & 127;
        Rs[r * 132 + c] = g_r2[(m0 + r) * H_ + c];
    }
    for (int i = tid; i < 128 * 128; i += 256) {
        int k = i >> 7, c = i & 127;
        Ws[i] = Wout[(size_t)k * V_ + n0 + c];
    }
    __syncthreads();

    float acc[4][8];
    #pragma unroll
    for (int r = 0; r < 4; r++)
        #pragma unroll
        for (int j = 0; j < 8; j++) acc[r][j] = 0.f;
    #pragma unroll 8
    for (int k = 0; k < 128; k++) {
        float a[4], bbv[8];
        #pragma unroll
        for (int r = 0; r < 4; r++) a[r] = Rs[(ty * 4 + r) * 132 + k];
        #pragma unroll
        for (int j = 0; j < 8; j++) bbv[j] = Ws[k * 128 + tx + 16 * j];
        #pragma unroll
        for (int r = 0; r < 4; r++)
            #pragma unroll
            for (int j = 0; j < 8; j++) acc[r][j] = fmaf(a[r], bbv[j], acc[r][j]);
    }
    #pragma unroll
    for (int r = 0; r < 4; r++)
        #pragma unroll
        for (int j = 0; j < 8; j++) {
            int rr = m0 + ty * 4 + r, cc = n0 + tx + 16 * j;
            out[(size_t)rr * V_ + cc] = acc[r][j] + bout[cc];
        }
}

// =====================================================================
// launcher
// =====================================================================
extern "C" void kernel_launch(void* const* d_in, const int* in_sizes, int n_in,
                              void* d_out, int out_size)
{
    const int*   seq   = (const int*)  d_in[0];
    const float* embed = (const float*)d_in[1];
    const float* W1    = (const float*)d_in[2];
    const float* b1    = (const float*)d_in[3];
    const float* W2    = (const float*)d_in[4];
    const float* b2    = (const float*)d_in[5];
    const float* gamma = (const float*)d_in[6];
    const float* beta  = (const float*)d_in[7];
    const float* Wrp   = (const float*)d_in[8];
    const float* brp   = (const float*)d_in[9];
    const float* Wout  = (const float*)d_in[10];
    const float* bout  = (const float*)d_in[11];
    float* out = (float*)d_out;

    const int PROJ_SMEM = (64 * 132 + 128 * 128) * 4;

    cudaFuncSetAttribute(encode_mma,   cudaFuncAttributeMaxDynamicSharedMemorySize, ENC_SMEM);
    cudaFuncSetAttribute(rproj_kernel, cudaFuncAttributeMaxDynamicSharedMemorySize, PROJ_SMEM);
    cudaFuncSetAttribute(out_kernel,   cudaFuncAttributeMaxDynamicSharedMemorySize, PROJ_SMEM);

    // profiling alignment: keep ncu's skip-window on the scan
    dummy_kernel<<<1, 32>>>();
    dummy_kernel<<<1, 32>>>();

    encode_mma<<<(B_ * L_) / 64, 256, ENC_SMEM>>>(seq, embed, W1, b1, W2, b2, gamma, beta);
    scan_kernel<<<B_, 256>>>();
    rproj_kernel<<<B_ / 64, 256, PROJ_SMEM>>>(Wrp, brp);
    out_kernel<<<dim3(V_ / 128, B_ / 64), 256, PROJ_SMEM>>>(Wout, bout, out);
}

// round 10
// speedup vs baseline: 1.0611x; 1.0492x over previous
#include <cuda_runtime.h>
#include <cstdint>
#include <cstddef>

#define B_  256
#define L_  2048
#define H_  128
#define H2_ 256
#define V_  32000
#define TB  64        // tokens per encode block

// ---------------- scratch (static device globals; no allocs allowed) ----------------
__device__ float g_h[(size_t)B_ * L_ * H_];   // encoded h_all [B,L,H]
__device__ float g_r[B_ * H_];
__device__ float g_r2[B_ * H_];

// ============ packed f32x2 helpers (FFMA2 — Blackwell, PTX-only path) ============
__device__ __forceinline__ uint64_t pk2(float lo, float hi) {
    uint64_t r;
    asm("mov.b64 %0, {%1, %2};" : "=l"(r) : "f"(lo), "f"(hi));
    return r;
}
__device__ __forceinline__ void upk2(uint64_t v, float& lo, float& hi) {
    asm("mov.b64 {%0, %1}, %2;" : "=f"(lo), "=f"(hi) : "l"(v));
}
__device__ __forceinline__ uint64_t fma2(uint64_t a, uint64_t b, uint64_t c) {
    uint64_t d;
    asm("fma.rn.f32x2 %0, %1, %2, %3;" : "=l"(d) : "l"(a), "l"(b), "l"(c));
    return d;
}

// ---------------- profiling-alignment dummy ----------------
__global__ void dummy_kernel() {}

// =====================================================================
// Encode (FFMA2): R1's exact scalar arithmetic, independent column
// chains packed pairwise into f32x2 -> bit-identical to R1 output.
// 64 tokens/CTA, 256 threads.
// =====================================================================
#define ENC_SMEM ((64 * 132 + 64 * 260 + 32 * 256) * 4)   // 133120 B

__global__ void __launch_bounds__(256, 1) encode_ffma2(
    const int*   __restrict__ seq,   const float* __restrict__ embed,
    const float* __restrict__ W1,    const float* __restrict__ b1,
    const float* __restrict__ W2,    const float* __restrict__ b2,
    const float* __restrict__ gamma, const float* __restrict__ beta)
{
    extern __shared__ float sm[];
    float* Es = sm;               // [64][132]
    float* Us = Es + 64 * 132;    // [64][260] (u), reused as y [64][132]
    float* Ws = Us + 64 * 260;    // weight chunk, up to [32][256]

    const int tid = threadIdx.x;
    const int ty  = tid >> 4;     // 0..15
    const int tx  = tid & 15;     // 0..15
    const int tok0 = blockIdx.x * TB;

    // ---- gather embeddings ----
    for (int i = tid; i < TB * H_; i += 256) {
        int row = i >> 7, col = i & 127;
        int s = seq[tok0 + row];
        Es[row * 132 + col] = embed[(size_t)s * H_ + col];
    }

    // ---- GEMM1: u = relu(e @ W1 + b1)   (64x256, K=128) — packed pairs ----
    uint64_t acc[4][8];
    #pragma unroll
    for (int r = 0; r < 4; r++)
        #pragma unroll
        for (int j = 0; j < 8; j++) acc[r][j] = 0ull;

    for (int kc = 0; kc < H_; kc += 32) {
        __syncthreads();
        for (int i = tid; i < 32 * H2_; i += 256) {
            int rr = i >> 8, cc = i & 255;
            Ws[i] = W1[(kc + rr) * H2_ + cc];
        }
        __syncthreads();
        #pragma unroll 8
        for (int kk = 0; kk < 32; kk++) {
            uint64_t a2[4], b2v[8];
            #pragma unroll
            for (int r = 0; r < 4; r++) {
                float a = Es[(ty * 4 + r) * 132 + kc + kk];
                a2[r] = pk2(a, a);
            }
            #pragma unroll
            for (int j = 0; j < 8; j++)
                b2v[j] = pk2(Ws[kk * H2_ + tx + 16 * (2 * j)],
                             Ws[kk * H2_ + tx + 16 * (2 * j + 1)]);
            #pragma unroll
            for (int r = 0; r < 4; r++)
                #pragma unroll
                for (int j = 0; j < 8; j++) acc[r][j] = fma2(a2[r], b2v[j], acc[r][j]);
        }
    }
    __syncthreads();
    #pragma unroll
    for (int r = 0; r < 4; r++)
        #pragma unroll
        for (int j = 0; j < 8; j++) {
            float x0, x1;
            upk2(acc[r][j], x0, x1);
            int col0 = tx + 16 * (2 * j), col1 = tx + 16 * (2 * j + 1);
            Us[(ty * 4 + r) * 260 + col0] = fmaxf(x0 + b1[col0], 0.f);
            Us[(ty * 4 + r) * 260 + col1] = fmaxf(x1 + b1[col1], 0.f);
        }

    // ---- GEMM2: y = u @ W2 + b2 + e   (64x128, K=256) — packed pairs ----
    uint64_t acc2[4][4];
    #pragma unroll
    for (int r = 0; r < 4; r++)
        #pragma unroll
        for (int j = 0; j < 4; j++) acc2[r][j] = 0ull;

    for (int kc = 0; kc < H2_; kc += 32) {
        __syncthreads();
        for (int i = tid; i < 32 * H_; i += 256) {
            int rr = i >> 7, cc = i & 127;
            Ws[i] = W2[(kc + rr) * H_ + cc];
        }
        __syncthreads();
        #pragma unroll 8
        for (int kk = 0; kk < 32; kk++) {
            uint64_t a2[4], b2v[4];
            #pragma unroll
            for (int r = 0; r < 4; r++) {
                float a = Us[(ty * 4 + r) * 260 + kc + kk];
                a2[r] = pk2(a, a);
            }
            #pragma unroll
            for (int j = 0; j < 4; j++)
                b2v[j] = pk2(Ws[kk * H_ + tx + 16 * (2 * j)],
                             Ws[kk * H_ + tx + 16 * (2 * j + 1)]);
            #pragma unroll
            for (int r = 0; r < 4; r++)
                #pragma unroll
                for (int j = 0; j < 4; j++) acc2[r][j] = fma2(a2[r], b2v[j], acc2[r][j]);
        }
    }
    __syncthreads();   // all Us (u) reads done before overwriting with y
    #pragma unroll
    for (int r = 0; r < 4; r++)
        #pragma unroll
        for (int j = 0; j < 4; j++) {
            float x0, x1;
            upk2(acc2[r][j], x0, x1);
            int row = ty * 4 + r;
            int col0 = tx + 16 * (2 * j), col1 = tx + 16 * (2 * j + 1);
            Us[row * 132 + col0] = x0 + b2[col0] + Es[row * 132 + col0];
            Us[row * 132 + col1] = x1 + b2[col1] + Es[row * 132 + col1];
        }
    __syncthreads();

    // ---- LayerNorm: 8 warps x 8 rows (verbatim R1) ----
    const int wid = tid >> 5, lane = tid & 31;
    #pragma unroll
    for (int rr = 0; rr < 8; rr++) {
        int row = wid * 8 + rr;
        float v[4];
        #pragma unroll
        for (int q = 0; q < 4; q++) v[q] = Us[row * 132 + lane + 32 * q];
        float s = v[0] + v[1] + v[2] + v[3];
        #pragma unroll
        for (int o = 16; o; o >>= 1) s += __shfl_xor_sync(0xffffffffu, s, o);
        float mu = s * (1.f / 128.f);
        float d[4], sq = 0.f;
        #pragma unroll
        for (int q = 0; q < 4; q++) { d[q] = v[q] - mu; sq = fmaf(d[q], d[q], sq); }
        #pragma unroll
        for (int o = 16; o; o >>= 1) sq += __shfl_xor_sync(0xffffffffu, sq, o);
        float inv = rsqrtf(sq * (1.f / 128.f) + 1e-5f);
        size_t base = (size_t)(tok0 + row) * H_;
        #pragma unroll
        for (int q = 0; q < 4; q++) {
            int col = lane + 32 * q;
            g_h[base + col] = d[q] * inv * gamma[col] + beta[col];
        }
    }
}

// =====================================================================
// Scan v5 (unchanged from R8 — chain-identical to R1's scan, passed)
// =====================================================================
__global__ void __launch_bounds__(256, 2) scan_kernel()
{
    __shared__ float k_s[2][128];
    __shared__ float red_k[2][4];
    __shared__ float err_s[128];
    __shared__ float red_e[4];
    __shared__ float vp_part[128][17];

    const int bb   = blockIdx.x;
    const int tid  = threadIdx.x;
    const int ty   = tid >> 4, tx = tid & 15;
    const int lane = tid & 31;
    const float* __restrict__ hb = g_h + (size_t)bb * L_ * H_;

    uint64_t M2[4][8];
    #pragma unroll
    for (int p = 0; p < 4; p++)
        #pragma unroll
        for (int c = 0; c < 8; c++) M2[p][c] = 0ull;

    float kn0 = 0.f, kn1 = 0.f;
    if (tid >= 128) {
        const int i = tid - 128;
        float kv = hb[i];
        k_s[0][i] = kv;
        float p = kv * kv;
        #pragma unroll
        for (int o = 16; o; o >>= 1) p += __shfl_xor_sync(0xffffffffu, p, o);
        if (lane == 0) red_k[0][i >> 5] = p;
        kn0 = hb[128 + i];
        kn1 = hb[256 + i];
    }
    __syncthreads();

    for (int t = 0; t < L_ - 1; t++) {
        const int buf = t & 1;

        float kreg[8];
        uint64_t k2[8];
        #pragma unroll
        for (int c = 0; c < 8; c++) {
            kreg[c] = k_s[buf][tx * 8 + c];
            k2[c]   = pk2(kreg[c], kreg[c]);
        }
        #pragma unroll
        for (int p = 0; p < 4; p++) {
            uint64_t s2 = 0ull;
            #pragma unroll
            for (int c = 0; c < 8; c++) s2 = fma2(M2[p][c], k2[c], s2);
            float slo, shi;
            upk2(s2, slo, shi);
            vp_part[ty * 8 + 2 * p][tx]     = slo;
            vp_part[ty * 8 + 2 * p + 1][tx] = shi;
        }
        if (tid >= 128) {
            const int i = tid - 128;
            k_s[buf ^ 1][i] = kn0;
            float p = kn0 * kn0;
            #pragma unroll
            for (int o = 16; o; o >>= 1) p += __shfl_xor_sync(0xffffffffu, p, o);
            if (lane == 0) red_k[buf ^ 1][i >> 5] = p;
            kn0 = kn1;
            kn1 = (t + 3 < L_) ? hb[(size_t)(t + 3) * H_ + i] : 0.f;
        }
        __syncthreads();                          // A

        const float kk = red_k[buf][0] + red_k[buf][1] + red_k[buf][2] + red_k[buf][3];

        if (tid < 128) {
            float vp = 0.f;
            #pragma unroll
            for (int x = 0; x < 16; x++) vp += vp_part[tid][x];
            float e = k_s[buf][tid] - vp / (kk + 1e-6f);
            err_s[tid] = e;
            float p = e * e;
            #pragma unroll
            for (int o = 16; o; o >>= 1) p += __shfl_xor_sync(0xffffffffu, p, o);
            if (lane == 0) red_e[tid >> 5] = p;
        }
        __syncthreads();                          // B

        float e2 = red_e[0] + red_e[1] + red_e[2] + red_e[3];
        if (sqrtf(e2) > 0.4f * sqrtf(kk)) {
            #pragma unroll
            for (int p = 0; p < 4; p++) {
                uint64_t er2 = pk2(err_s[ty * 8 + 2 * p], err_s[ty * 8 + 2 * p + 1]);
                #pragma unroll
                for (int c = 0; c < 8; c++) M2[p][c] = fma2(er2, k2[c], M2[p][c]);
            }
        }
    }

    {
        const int buf = (L_ - 1) & 1;
        uint64_t k2[8];
        #pragma unroll
        for (int c = 0; c < 8; c++) {
            float kv = k_s[buf][tx * 8 + c];
            k2[c] = pk2(kv, kv);
        }
        #pragma unroll
        for (int p = 0; p < 4; p++) {
            uint64_t s2 = 0ull;
            #pragma unroll
            for (int c = 0; c < 8; c++) s2 = fma2(M2[p][c], k2[c], s2);
            float slo, shi;
            upk2(s2, slo, shi);
            vp_part[ty * 8 + 2 * p][tx]     = slo;
            vp_part[ty * 8 + 2 * p + 1][tx] = shi;
        }
        __syncthreads();
        if (tid < 128) {
            float vp = 0.f;
            #pragma unroll
            for (int x = 0; x < 16; x++) vp += vp_part[tid][x];
            g_r[bb * H_ + tid] = vp;
        }
    }
}

// =====================================================================
// Kernel 3: r2 = r @ Wrp + brp
// =====================================================================
__global__ void __launch_bounds__(256, 1) rproj_kernel(
    const float* __restrict__ Wrp, const float* __restrict__ brp)
{
    extern __shared__ float smf[];
    float* Rs = smf;
    float* Ws = smf + 64 * 132;
    const int tid = threadIdx.x, ty = tid >> 4, tx = tid & 15;
    const int m0 = blockIdx.x * 64;

    for (int i = tid; i < 64 * 128; i += 256) {
        int r = i >> 7, c = i & 127;
        Rs[r * 132 + c] = g_r[(m0 + r) * H_ + c];
    }
    for (int i = tid; i < 128 * 128; i += 256) Ws[i] = Wrp[i];
    __syncthreads();

    float acc[4][8];
    #pragma unroll
    for (int r = 0; r < 4; r++)
        #pragma unroll
        for (int j = 0; j < 8; j++) acc[r][j] = 0.f;
    #pragma unroll 8
    for (int k = 0; k < 128; k++) {
        float a[4], bbv[8];
        #pragma unroll
        for (int r = 0; r < 4; r++) a[r] = Rs[(ty * 4 + r) * 132 + k];
        #pragma unroll
        for (int j = 0; j < 8; j++) bbv[j] = Ws[k * 128 + tx + 16 * j];
        #pragma unroll
        for (int r = 0; r < 4; r++)
            #pragma unroll
            for (int j = 0; j < 8; j++) acc[r][j] = fmaf(a[r], bbv[j], acc[r][j]);
    }
    #pragma unroll
    for (int r = 0; r < 4; r++)
        #pragma unroll
        for (int j = 0; j < 8; j++) {
            int rr = m0 + ty * 4 + r, cc = tx + 16 * j;
            g_r2[rr * H_ + cc] = acc[r][j] + brp[cc];
        }
}

// =====================================================================
// Kernel 4: out = r2 @ Wout + bout
// =====================================================================
__global__ void __launch_bounds__(256, 1) out_kernel(
    const float* __restrict__ Wout, const float* __restrict__ bout,
    float* __restrict__ out)
{
    extern __shared__ float smf[];
    float* Rs = smf;
    float* Ws = smf + 64 * 132;
    const int tid = threadIdx.x, ty = tid >> 4, tx = tid & 15;
    const int n0 = blockIdx.x * 128;
    const int m0 = blockIdx.y * 64;

    for (int i = tid; i < 64 * 128; i += 256) {
        int r = i >> 7, c = i & 127;
        Rs[r * 132 + c] = g_r2[(m0 + r) * H_ + c];
    }
    for (int i = tid; i < 128 * 128; i += 256) {
        int k = i >> 7, c = i & 127;
        Ws[i] = Wout[(size_t)k * V_ + n0 + c];
    }
    __syncthreads();

    float acc[4][8];
    #pragma unroll
    for (int r = 0; r < 4; r++)
        #pragma unroll
        for (int j = 0; j < 8; j++) acc[r][j] = 0.f;
    #pragma unroll 8
    for (int k = 0; k < 128; k++) {
        float a[4], bbv[8];
        #pragma unroll
        for (int r = 0; r < 4; r++) a[r] = Rs[(ty * 4 + r) * 132 + k];
        #pragma unroll
        for (int j = 0; j < 8; j++) bbv[j] = Ws[k * 128 + tx + 16 * j];
        #pragma unroll
        for (int r = 0; r < 4; r++)
            #pragma unroll
            for (int j = 0; j < 8; j++) acc[r][j] = fmaf(a[r], bbv[j], acc[r][j]);
    }
    #pragma unroll
    for (int r = 0; r < 4; r++)
        #pragma unroll
        for (int j = 0; j < 8; j++) {
            int rr = m0 + ty * 4 + r, cc = n0 + tx + 16 * j;
            out[(size_t)rr * V_ + cc] = acc[r][j] + bout[cc];
        }
}

// =====================================================================
// launcher
// =====================================================================
extern "C" void kernel_launch(void* const* d_in, const int* in_sizes, int n_in,
                              void* d_out, int out_size)
{
    const int*   seq   = (const int*)  d_in[0];
    const float* embed = (const float*)d_in[1];
    const float* W1    = (const float*)d_in[2];
    const float* b1    = (const float*)d_in[3];
    const float* W2    = (const float*)d_in[4];
    const float* b2    = (const float*)d_in[5];
    const float* gamma = (const float*)d_in[6];
    const float* beta  = (const float*)d_in[7];
    const float* Wrp   = (const float*)d_in[8];
    const float* brp   = (const float*)d_in[9];
    const float* Wout  = (const float*)d_in[10];
    const float* bout  = (const float*)d_in[11];
    float* out = (float*)d_out;

    const int PROJ_SMEM = (64 * 132 + 128 * 128) * 4;

    cudaFuncSetAttribute(encode_ffma2, cudaFuncAttributeMaxDynamicSharedMemorySize, ENC_SMEM);
    cudaFuncSetAttribute(rproj_kernel, cudaFuncAttributeMaxDynamicSharedMemorySize, PROJ_SMEM);
    cudaFuncSetAttribute(out_kernel,   cudaFuncAttributeMaxDynamicSharedMemorySize, PROJ_SMEM);

    // profiling alignment: keep ncu's window on the scan
    dummy_kernel<<<1, 32>>>();
    dummy_kernel<<<1, 32>>>();

    encode_ffma2<<<(B_ * L_) / TB, 256, ENC_SMEM>>>(seq, embed, W1, b1, W2, b2, gamma, beta);
    scan_kernel<<<B_, 256>>>();
    rproj_kernel<<<B_ / 64, 256, PROJ_SMEM>>>(Wrp, brp);
    out_kernel<<<dim3(V_ / 128, B_ / 64), 256, PROJ_SMEM>>>(Wout, bout, out);
}

// round 11
// speedup vs baseline: 1.1504x; 1.0841x over previous
#include <cuda_runtime.h>
#include <cstdint>
#include <cstddef>

#define B_  256
#define L_  2048
#define H_  128
#define H2_ 256
#define V_  32000
#define TB  64        // tokens per encode block

// ---------------- scratch (static device globals; no allocs allowed) ----------------
__device__ float g_h[(size_t)B_ * L_ * H_];   // encoded h_all [B,L,H]
__device__ float g_r[B_ * H_];
__device__ float g_r2[B_ * H_];

// ============ packed f32x2 helpers (FFMA2 — Blackwell, PTX-only path) ============
__device__ __forceinline__ uint64_t pk2(float lo, float hi) {
    uint64_t r;
    asm("mov.b64 %0, {%1, %2};" : "=l"(r) : "f"(lo), "f"(hi));
    return r;
}
__device__ __forceinline__ void upk2(uint64_t v, float& lo, float& hi) {
    asm("mov.b64 {%0, %1}, %2;" : "=f"(lo), "=f"(hi) : "l"(v));
}
__device__ __forceinline__ uint64_t fma2(uint64_t a, uint64_t b, uint64_t c) {
    uint64_t d;
    asm("fma.rn.f32x2 %0, %1, %2, %3;" : "=l"(d) : "l"(a), "l"(b), "l"(c));
    return d;
}

// ---------------- profiling-alignment dummies ----------------
__global__ void dummy_kernel() {}

// =====================================================================
// Encode (FFMA2, LDS.64): R1's exact scalar chains; f32x2 lanes pair
// ADJACENT columns (32j+2tx, 32j+2tx+1) so b-operands load as float2.
// Pairing choice doesn't alter any per-column chain -> bit-identical.
// 64 tokens/CTA, 256 threads.
// =====================================================================
#define ENC_SMEM ((64 * 132 + 64 * 260 + 32 * 256) * 4)   // 133120 B

__global__ void __launch_bounds__(256, 1) encode_ffma2(
    const int*   __restrict__ seq,   const float* __restrict__ embed,
    const float* __restrict__ W1,    const float* __restrict__ b1,
    const float* __restrict__ W2,    const float* __restrict__ b2,
    const float* __restrict__ gamma, const float* __restrict__ beta)
{
    extern __shared__ float sm[];
    float* Es = sm;               // [64][132]
    float* Us = Es + 64 * 132;    // [64][260] (u), reused as y [64][132]
    float* Ws = Us + 64 * 260;    // weight chunk, up to [32][256]

    const int tid = threadIdx.x;
    const int ty  = tid >> 4;     // 0..15
    const int tx  = tid & 15;     // 0..15
    const int tok0 = blockIdx.x * TB;

    // ---- gather embeddings (float4) ----
    for (int i = tid; i < TB * 32; i += 256) {
        int row = i >> 5, q = i & 31;
        int s = seq[tok0 + row];
        float4 v = *(const float4*)(embed + (size_t)s * H_ + 4 * q);
        *(float4*)(Es + row * 132 + 4 * q) = v;
    }

    // ---- GEMM1: u = relu(e @ W1 + b1)   (64x256, K=128) — adjacent pairs ----
    uint64_t acc[4][8];
    #pragma unroll
    for (int r = 0; r < 4; r++)
        #pragma unroll
        for (int j = 0; j < 8; j++) acc[r][j] = 0ull;

    for (int kc = 0; kc < H_; kc += 32) {
        __syncthreads();
        {   // contiguous 32KB copy: W1 rows kc..kc+31 (float4)
            const float4* src = (const float4*)(W1 + kc * H2_);
            float4* dst = (float4*)Ws;
            for (int i = tid; i < 32 * H2_ / 4; i += 256) dst[i] = src[i];
        }
        __syncthreads();
        #pragma unroll 8
        for (int kk = 0; kk < 32; kk++) {
            uint64_t a2[4], b2v[8];
            #pragma unroll
            for (int r = 0; r < 4; r++) {
                float a = Es[(ty * 4 + r) * 132 + kc + kk];
                a2[r] = pk2(a, a);
            }
            #pragma unroll
            for (int j = 0; j < 8; j++) {
                float2 bw = *(const float2*)(Ws + kk * H2_ + 32 * j + 2 * tx);
                b2v[j] = pk2(bw.x, bw.y);
            }
            #pragma unroll
            for (int r = 0; r < 4; r++)
                #pragma unroll
                for (int j = 0; j < 8; j++) acc[r][j] = fma2(a2[r], b2v[j], acc[r][j]);
        }
    }
    __syncthreads();
    #pragma unroll
    for (int r = 0; r < 4; r++)
        #pragma unroll
        for (int j = 0; j < 8; j++) {
            float x0, x1;
            upk2(acc[r][j], x0, x1);
            int col0 = 32 * j + 2 * tx;
            float2 bb = *(const float2*)(b1 + col0);
            float2 uo;
            uo.x = fmaxf(x0 + bb.x, 0.f);
            uo.y = fmaxf(x1 + bb.y, 0.f);
            *(float2*)(Us + (ty * 4 + r) * 260 + col0) = uo;
        }

    // ---- GEMM2: y = u @ W2 + b2 + e   (64x128, K=256) — adjacent pairs ----
    uint64_t acc2[4][4];
    #pragma unroll
    for (int r = 0; r < 4; r++)
        #pragma unroll
        for (int j = 0; j < 4; j++) acc2[r][j] = 0ull;

    for (int kc = 0; kc < H2_; kc += 32) {
        __syncthreads();
        {   // contiguous 16KB copy: W2 rows kc..kc+31 (float4)
            const float4* src = (const float4*)(W2 + kc * H_);
            float4* dst = (float4*)Ws;
            for (int i = tid; i < 32 * H_ / 4; i += 256) dst[i] = src[i];
        }
        __syncthreads();
        #pragma unroll 8
        for (int kk = 0; kk < 32; kk++) {
            uint64_t a2[4], b2v[4];
            #pragma unroll
            for (int r = 0; r < 4; r++) {
                float a = Us[(ty * 4 + r) * 260 + kc + kk];
                a2[r] = pk2(a, a);
            }
            #pragma unroll
            for (int j = 0; j < 4; j++) {
                float2 bw = *(const float2*)(Ws + kk * H_ + 32 * j + 2 * tx);
                b2v[j] = pk2(bw.x, bw.y);
            }
            #pragma unroll
            for (int r = 0; r < 4; r++)
                #pragma unroll
                for (int j = 0; j < 4; j++) acc2[r][j] = fma2(a2[r], b2v[j], acc2[r][j]);
        }
    }
    __syncthreads();   // all Us (u) reads done before overwriting with y
    #pragma unroll
    for (int r = 0; r < 4; r++)
        #pragma unroll
        for (int j = 0; j < 4; j++) {
            float x0, x1;
            upk2(acc2[r][j], x0, x1);
            int row = ty * 4 + r;
            int col0 = 32 * j + 2 * tx;
            float2 bb = *(const float2*)(b2 + col0);
            float2 ee = *(const float2*)(Es + row * 132 + col0);
            float2 yo;
            yo.x = x0 + bb.x + ee.x;
            yo.y = x1 + bb.y + ee.y;
            *(float2*)(Us + row * 132 + col0) = yo;
        }
    __syncthreads();

    // ---- LayerNorm: 8 warps x 8 rows (verbatim R1) ----
    const int wid = tid >> 5, lane = tid & 31;
    #pragma unroll
    for (int rr = 0; rr < 8; rr++) {
        int row = wid * 8 + rr;
        float v[4];
        #pragma unroll
        for (int q = 0; q < 4; q++) v[q] = Us[row * 132 + lane + 32 * q];
        float s = v[0] + v[1] + v[2] + v[3];
        #pragma unroll
        for (int o = 16; o; o >>= 1) s += __shfl_xor_sync(0xffffffffu, s, o);
        float mu = s * (1.f / 128.f);
        float d[4], sq = 0.f;
        #pragma unroll
        for (int q = 0; q < 4; q++) { d[q] = v[q] - mu; sq = fmaf(d[q], d[q], sq); }
        #pragma unroll
        for (int o = 16; o; o >>= 1) sq += __shfl_xor_sync(0xffffffffu, sq, o);
        float inv = rsqrtf(sq * (1.f / 128.f) + 1e-5f);
        size_t base = (size_t)(tok0 + row) * H_;
        #pragma unroll
        for (int q = 0; q < 4; q++) {
            int col = lane + 32 * q;
            g_h[base + col] = d[q] * inv * gamma[col] + beta[col];
        }
    }
}

// =====================================================================
// Scan v5 (R8/R9 structure; k/err loads vectorized — pure loads, order-
// irrelevant -> still bit-identical to R1's chains)
// =====================================================================
__global__ void __launch_bounds__(256, 2) scan_kernel()
{
    __shared__ float k_s[2][128];
    __shared__ float red_k[2][4];
    __shared__ float err_s[128];
    __shared__ float red_e[4];
    __shared__ float vp_part[128][17];

    const int bb   = blockIdx.x;
    const int tid  = threadIdx.x;
    const int ty   = tid >> 4, tx = tid & 15;
    const int lane = tid & 31;
    const float* __restrict__ hb = g_h + (size_t)bb * L_ * H_;

    uint64_t M2[4][8];
    #pragma unroll
    for (int p = 0; p < 4; p++)
        #pragma unroll
        for (int c = 0; c < 8; c++) M2[p][c] = 0ull;

    float kn0 = 0.f, kn1 = 0.f;
    if (tid >= 128) {
        const int i = tid - 128;
        float kv = hb[i];
        k_s[0][i] = kv;
        float p = kv * kv;
        #pragma unroll
        for (int o = 16; o; o >>= 1) p += __shfl_xor_sync(0xffffffffu, p, o);
        if (lane == 0) red_k[0][i >> 5] = p;
        kn0 = hb[128 + i];
        kn1 = hb[256 + i];
    }
    __syncthreads();

    for (int t = 0; t < L_ - 1; t++) {
        const int buf = t & 1;

        float kreg[8];
        uint64_t k2[8];
        {
            float4 kA = *(const float4*)(&k_s[buf][tx * 8]);
            float4 kB = *(const float4*)(&k_s[buf][tx * 8 + 4]);
            kreg[0] = kA.x; kreg[1] = kA.y; kreg[2] = kA.z; kreg[3] = kA.w;
            kreg[4] = kB.x; kreg[5] = kB.y; kreg[6] = kB.z; kreg[7] = kB.w;
        }
        #pragma unroll
        for (int c = 0; c < 8; c++) k2[c] = pk2(kreg[c], kreg[c]);

        #pragma unroll
        for (int p = 0; p < 4; p++) {
            uint64_t s2 = 0ull;
            #pragma unroll
            for (int c = 0; c < 8; c++) s2 = fma2(M2[p][c], k2[c], s2);
            float slo, shi;
            upk2(s2, slo, shi);
            vp_part[ty * 8 + 2 * p][tx]     = slo;
            vp_part[ty * 8 + 2 * p + 1][tx] = shi;
        }
        if (tid >= 128) {
            const int i = tid - 128;
            k_s[buf ^ 1][i] = kn0;
            float p = kn0 * kn0;
            #pragma unroll
            for (int o = 16; o; o >>= 1) p += __shfl_xor_sync(0xffffffffu, p, o);
            if (lane == 0) red_k[buf ^ 1][i >> 5] = p;
            kn0 = kn1;
            kn1 = (t + 3 < L_) ? hb[(size_t)(t + 3) * H_ + i] : 0.f;
        }
        __syncthreads();                          // A

        const float kk = red_k[buf][0] + red_k[buf][1] + red_k[buf][2] + red_k[buf][3];

        if (tid < 128) {
            float vp = 0.f;
            #pragma unroll
            for (int x = 0; x < 16; x++) vp += vp_part[tid][x];
            float e = k_s[buf][tid] - vp / (kk + 1e-6f);
            err_s[tid] = e;
            float p = e * e;
            #pragma unroll
            for (int o = 16; o; o >>= 1) p += __shfl_xor_sync(0xffffffffu, p, o);
            if (lane == 0) red_e[tid >> 5] = p;
        }
        __syncthreads();                          // B

        float e2 = red_e[0] + red_e[1] + red_e[2] + red_e[3];
        if (sqrtf(e2) > 0.4f * sqrtf(kk)) {
            #pragma unroll
            for (int p = 0; p < 4; p++) {
                float2 ep = *(const float2*)(&err_s[ty * 8 + 2 * p]);
                uint64_t er2 = pk2(ep.x, ep.y);
                #pragma unroll
                for (int c = 0; c < 8; c++) M2[p][c] = fma2(er2, k2[c], M2[p][c]);
            }
        }
    }

    {
        const int buf = (L_ - 1) & 1;
        uint64_t k2[8];
        {
            float4 kA = *(const float4*)(&k_s[buf][tx * 8]);
            float4 kB = *(const float4*)(&k_s[buf][tx * 8 + 4]);
            k2[0] = pk2(kA.x, kA.x); k2[1] = pk2(kA.y, kA.y);
            k2[2] = pk2(kA.z, kA.z); k2[3] = pk2(kA.w, kA.w);
            k2[4] = pk2(kB.x, kB.x); k2[5] = pk2(kB.y, kB.y);
            k2[6] = pk2(kB.z, kB.z); k2[7] = pk2(kB.w, kB.w);
        }
        #pragma unroll
        for (int p = 0; p < 4; p++) {
            uint64_t s2 = 0ull;
            #pragma unroll
            for (int c = 0; c < 8; c++) s2 = fma2(M2[p][c], k2[c], s2);
            float slo, shi;
            upk2(s2, slo, shi);
            vp_part[ty * 8 + 2 * p][tx]     = slo;
            vp_part[ty * 8 + 2 * p + 1][tx] = shi;
        }
        __syncthreads();
        if (tid < 128) {
            float vp = 0.f;
            #pragma unroll
            for (int x = 0; x < 16; x++) vp += vp_part[tid][x];
            g_r[bb * H_ + tid] = vp;
        }
    }
}

// =====================================================================
// Kernel 3: r2 = r @ Wrp + brp
// =====================================================================
__global__ void __launch_bounds__(256, 1) rproj_kernel(
    const float* __restrict__ Wrp, const float* __restrict__ brp)
{
    extern __shared__ float smf[];
    float* Rs = smf;
    float* Ws = smf + 64 * 132;
    const int tid = threadIdx.x, ty = tid >> 4, tx = tid & 15;
    const int m0 = blockIdx.x * 64;

    for (int i = tid; i < 64 * 128; i += 256) {
        int r = i >> 7, c = i & 127;
        Rs[r * 132 + c] = g_r[(m0 + r) * H_ + c];
    }
    for (int i = tid; i < 128 * 128; i += 256) Ws[i] = Wrp[i];
    __syncthreads();

    float acc[4][8];
    #pragma unroll
    for (int r = 0; r < 4; r++)
        #pragma unroll
        for (int j = 0; j < 8; j++) acc[r][j] = 0.f;
    #pragma unroll 8
    for (int k = 0; k < 128; k++) {
        float a[4], bbv[8];
        #pragma unroll
        for (int r = 0; r < 4; r++) a[r] = Rs[(ty * 4 + r) * 132 + k];
        #pragma unroll
        for (int j = 0; j < 8; j++) bbv[j] = Ws[k * 128 + tx + 16 * j];
        #pragma unroll
        for (int r = 0; r < 4; r++)
            #pragma unroll
            for (int j = 0; j < 8; j++) acc[r][j] = fmaf(a[r], bbv[j], acc[r][j]);
    }
    #pragma unroll
    for (int r = 0; r < 4; r++)
        #pragma unroll
        for (int j = 0; j < 8; j++) {
            int rr = m0 + ty * 4 + r, cc = tx + 16 * j;
            g_r2[rr * H_ + cc] = acc[r][j] + brp[cc];
        }
}

// =====================================================================
// Kernel 4: out = r2 @ Wout + bout
// =====================================================================
__global__ void __launch_bounds__(256, 1) out_kernel(
    const float* __restrict__ Wout, const float* __restrict__ bout,
    float* __restrict__ out)
{
    extern __shared__ float smf[];
    float* Rs = smf;
    float* Ws = smf + 64 * 132;
    const int tid = threadIdx.x, ty = tid >> 4, tx = tid & 15;
    const int n0 = blockIdx.x * 128;
    const int m0 = blockIdx.y * 64;

    for (int i = tid; i < 64 * 128; i += 256) {
        int r = i >> 7, c = i & 127;
        Rs[r * 132 + c] = g_r2[(m0 + r) * H_ + c];
    }
    for (int i = tid; i < 128 * 128; i += 256) {
        int k = i >> 7, c = i & 127;
        Ws[i] = Wout[(size_t)k * V_ + n0 + c];
    }
    __syncthreads();

    float acc[4][8];
    #pragma unroll
    for (int r = 0; r < 4; r++)
        #pragma unroll
        for (int j = 0; j < 8; j++) acc[r][j] = 0.f;
    #pragma unroll 8
    for (int k = 0; k < 128; k++) {
        float a[4], bbv[8];
        #pragma unroll
        for (int r = 0; r < 4; r++) a[r] = Rs[(ty * 4 + r) * 132 + k];
        #pragma unroll
        for (int j = 0; j < 8; j++) bbv[j] = Ws[k * 128 + tx + 16 * j];
        #pragma unroll
        for (int r = 0; r < 4; r++)
            #pragma unroll
            for (int j = 0; j < 8; j++) acc[r][j] = fmaf(a[r], bbv[j], acc[r][j]);
    }
    #pragma unroll
    for (int r = 0; r < 4; r++)
        #pragma unroll
        for (int j = 0; j < 8; j++) {
            int rr = m0 + ty * 4 + r, cc = n0 + tx + 16 * j;
            out[(size_t)rr * V_ + cc] = acc[r][j] + bout[cc];
        }
}

// =====================================================================
// launcher
// =====================================================================
extern "C" void kernel_launch(void* const* d_in, const int* in_sizes, int n_in,
                              void* d_out, int out_size)
{
    const int*   seq   = (const int*)  d_in[0];
    const float* embed = (const float*)d_in[1];
    const float* W1    = (const float*)d_in[2];
    const float* b1    = (const float*)d_in[3];
    const float* W2    = (const float*)d_in[4];
    const float* b2    = (const float*)d_in[5];
    const float* gamma = (const float*)d_in[6];
    const float* beta  = (const float*)d_in[7];
    const float* Wrp   = (const float*)d_in[8];
    const float* brp   = (const float*)d_in[9];
    const float* Wout  = (const float*)d_in[10];
    const float* bout  = (const float*)d_in[11];
    float* out = (float*)d_out;

    const int PROJ_SMEM = (64 * 132 + 128 * 128) * 4;

    cudaFuncSetAttribute(encode_ffma2, cudaFuncAttributeMaxDynamicSharedMemorySize, ENC_SMEM);
    cudaFuncSetAttribute(rproj_kernel, cudaFuncAttributeMaxDynamicSharedMemorySize, PROJ_SMEM);
    cudaFuncSetAttribute(out_kernel,   cudaFuncAttributeMaxDynamicSharedMemorySize, PROJ_SMEM);

    // profiling alignment: 3 dummies put ncu's -s 5 window on encode_ffma2
    dummy_kernel<<<1, 32>>>();
    dummy_kernel<<<1, 32>>>();
    dummy_kernel<<<1, 32>>>();

    encode_ffma2<<<(B_ * L_) / TB, 256, ENC_SMEM>>>(seq, embed, W1, b1, W2, b2, gamma, beta);
    scan_kernel<<<B_, 256>>>();
    rproj_kernel<<<B_ / 64, 256, PROJ_SMEM>>>(Wrp, brp);
    out_kernel<<<dim3(V_ / 128, B_ / 64), 256, PROJ_SMEM>>>(Wout, bout, out);
}